// round 14
// baseline (speedup 1.0000x reference)
#include <cuda_runtime.h>
#include <math.h>

// Problem shape
#define HDIM     4096
#define EDIM     64
#define M_TOTAL  16384

// Tiling: grid 128 (1 CTA/SM), **128 threads** (1 warp/SMSP),
// thread tile = 8 rows x 8 experts -> 32 FFMA2 per kk (max run length).
#define BM        128
#define KT        32
#define NT        (HDIM / KT)       // 128 K-tiles
#define NTHREADS  128

__global__ __launch_bounds__(NTHREADS, 1)
void router_kernel(const float* __restrict__ x,
                   const float* __restrict__ w,
                   float* __restrict__ out)
{
    // XOR-swizzled tiles (no padding): element (kk, r) at [kk][r ^ ((kk>>2 & 7)<<2)].
    // STS transpose conflict-free (bank = r ^ 4*k4 is a 32-bijection per warp);
    // LDS of aligned 4-row groups stays contiguous (XOR touches bits [2:5) only).
    __shared__ union {
        struct {
            float xs[KT][BM];      // 16 KB
            float ws[KT][EDIM];    //  8 KB
        } t;
        float ls[BM][EDIM + 4];    // epilogue logits tile (stride 68)
    } sm;

    const int tid = threadIdx.x;
    const int m0  = blockIdx.x * BM;

    // compute mapping: thread tile = 8 rows x 8 experts
    const int eg = tid & 7;            // experts 8*eg .. 8*eg+7
    const int rg = tid >> 3;           // rows    8*rg .. 8*rg+7   (0..15)

    // x global-load mapping: 8 float4 per thread per tile
    const int xk4   = tid & 7;         // float4 index in K within tile (0..7)
    const int xrow0 = tid >> 3;        // row 0..15, +16*i (i<8)

    // w global-load mapping: 4 float4 per thread per tile
    const int wk4 = tid & 7;
    const int we0 = tid >> 3;          // expert 0..15, +16*i (i<4)

    // swizzle constants on the store side
    const int xsw = 4 * xk4;
    const int wsw = 4 * wk4;

    // accumulators: acc[row_pair][expert], packed f32x2 over (row, row+1)
    unsigned long long acc[4][8];
    #pragma unroll
    for (int i = 0; i < 4; i++)
        #pragma unroll
        for (int j = 0; j < 8; j++)
            acc[i][j] = 0ull;

    float4 xv[8], wv[4];

    // prefetch tile 0 into registers
    {
        const float* xp = x + (size_t)m0 * HDIM + 4 * xk4;
        #pragma unroll
        for (int i = 0; i < 8; i++)
            xv[i] = *(const float4*)(xp + (size_t)(xrow0 + 16 * i) * HDIM);
        const float* wp = w + 4 * wk4;
        #pragma unroll
        for (int i = 0; i < 4; i++)
            wv[i] = *(const float4*)(wp + (size_t)(we0 + 16 * i) * HDIM);
    }

    for (int t = 0; t < NT; t++) {
        // ---- store prefetched tile to smem (swizzled transpose, conflict-free) ----
        #pragma unroll
        for (int i = 0; i < 8; i++) {
            int rs = (xrow0 + 16 * i) ^ xsw;
            sm.t.xs[4 * xk4 + 0][rs] = xv[i].x;
            sm.t.xs[4 * xk4 + 1][rs] = xv[i].y;
            sm.t.xs[4 * xk4 + 2][rs] = xv[i].z;
            sm.t.xs[4 * xk4 + 3][rs] = xv[i].w;
        }
        #pragma unroll
        for (int i = 0; i < 4; i++) {
            int es = (we0 + 16 * i) ^ wsw;
            sm.t.ws[4 * wk4 + 0][es] = wv[i].x;
            sm.t.ws[4 * wk4 + 1][es] = wv[i].y;
            sm.t.ws[4 * wk4 + 2][es] = wv[i].z;
            sm.t.ws[4 * wk4 + 3][es] = wv[i].w;
        }
        __syncthreads();

        // ---- prefetch next global tile (overlaps the whole compute phase) ----
        if (t + 1 < NT) {
            const int k0 = (t + 1) * KT;
            const float* xp = x + (size_t)m0 * HDIM + k0 + 4 * xk4;
            #pragma unroll
            for (int i = 0; i < 8; i++)
                xv[i] = *(const float4*)(xp + (size_t)(xrow0 + 16 * i) * HDIM);
            const float* wp = w + k0 + 4 * wk4;
            #pragma unroll
            for (int i = 0; i < 4; i++)
                wv[i] = *(const float4*)(wp + (size_t)(we0 + 16 * i) * HDIM);
        }

        // ---- mainloop: 32 kk steps, 32 FFMA2 each (4 LDS.128 + 8 mov + 32 FFMA2) ----
        #pragma unroll
        for (int kk = 0; kk < KT; kk++) {
            const int c  = ((kk >> 2) & 7) << 2;    // compile-time per unrolled kk
            const int r1 = (8 * rg) ^ c;
            const int e1 = (8 * eg) ^ c;
            ulonglong2 xa = *(const ulonglong2*)&sm.t.xs[kk][r1];
            ulonglong2 xb = *(const ulonglong2*)&sm.t.xs[kk][r1 ^ 4];
            float4 wfa = *(const float4*)&sm.t.ws[kk][e1];
            float4 wfb = *(const float4*)&sm.t.ws[kk][e1 ^ 4];

            unsigned long long xr[4];
            xr[0] = xa.x; xr[1] = xa.y; xr[2] = xb.x; xr[3] = xb.y;

            unsigned long long wd[8];
            asm("mov.b64 %0, {%1,%1};" : "=l"(wd[0]) : "r"(__float_as_uint(wfa.x)));
            asm("mov.b64 %0, {%1,%1};" : "=l"(wd[1]) : "r"(__float_as_uint(wfa.y)));
            asm("mov.b64 %0, {%1,%1};" : "=l"(wd[2]) : "r"(__float_as_uint(wfa.z)));
            asm("mov.b64 %0, {%1,%1};" : "=l"(wd[3]) : "r"(__float_as_uint(wfa.w)));
            asm("mov.b64 %0, {%1,%1};" : "=l"(wd[4]) : "r"(__float_as_uint(wfb.x)));
            asm("mov.b64 %0, {%1,%1};" : "=l"(wd[5]) : "r"(__float_as_uint(wfb.y)));
            asm("mov.b64 %0, {%1,%1};" : "=l"(wd[6]) : "r"(__float_as_uint(wfb.z)));
            asm("mov.b64 %0, {%1,%1};" : "=l"(wd[7]) : "r"(__float_as_uint(wfb.w)));

            #pragma unroll
            for (int rp = 0; rp < 4; rp++)
                #pragma unroll
                for (int e = 0; e < 8; e++)
                    asm("fma.rn.f32x2 %0, %1, %2, %0;"
                        : "+l"(acc[rp][e])
                        : "l"(xr[rp]), "l"(wd[e]));
        }
        __syncthreads();
    }

    // ---- epilogue ----
    float* logits_out = out;
    float* idx_out    = out + (size_t)M_TOTAL * EDIM;
    float* p_out      = idx_out + (size_t)M_TOTAL * 2;

    // rows here are UNswizzled — mainloop done, smem repurposed
    #pragma unroll
    for (int rp = 0; rp < 4; rp++) {
        #pragma unroll
        for (int e = 0; e < 8; e++) {
            unsigned int lo, hi;
            asm("mov.b64 {%0,%1}, %2;" : "=r"(lo), "=r"(hi) : "l"(acc[rp][e]));
            int r   = 8 * rg + 2 * rp;
            int col = 8 * eg + e;
            sm.ls[r][col]     = __uint_as_float(lo);
            sm.ls[r + 1][col] = __uint_as_float(hi);
        }
    }
    __syncthreads();

    // coalesced logits store: 16 x float4 per thread
    #pragma unroll
    for (int q = 0; q < 16; q++) {
        int idx = tid + NTHREADS * q;       // 0..2047 float4 slots
        int row = idx >> 4;
        int c4  = idx & 15;
        float4 v = *(const float4*)&sm.ls[row][c4 * 4];
        *(float4*)&logits_out[(size_t)(m0 + row) * EDIM + c4 * 4] = v;
    }

    // one thread per row: stable top-2 (strict >, ties -> lower index = lax.top_k)
    {
        const float* r = &sm.ls[tid][0];
        float best = -INFINITY, sec = -INFINITY;
        int bi = 0, si = 0;
        #pragma unroll 8
        for (int i = 0; i < EDIM; i++) {
            float v = r[i];
            if (v > best) { sec = best; si = bi; best = v; bi = i; }
            else if (v > sec) { sec = v; si = i; }
        }
        float tt  = expf(sec - best);
        float inv = 1.0f / (1.0f + tt);
        size_t m = (size_t)(m0 + tid);
        idx_out[m * 2 + 0] = (float)bi;
        idx_out[m * 2 + 1] = (float)si;
        p_out[m * 2 + 0]   = inv;
        p_out[m * 2 + 1]   = tt * inv;
    }
}

extern "C" void kernel_launch(void* const* d_in, const int* in_sizes, int n_in,
                              void* d_out, int out_size)
{
    const float* x  = (const float*)d_in[0];
    const float* gw = (const float*)d_in[1];
    // defensive: identify tensors by size (x = 67108864, gate_w = 262144)
    if (n_in >= 2 && in_sizes[0] < in_sizes[1]) {
        const float* tmp = x; x = gw; gw = tmp;
    }
    router_kernel<<<M_TOTAL / BM, NTHREADS>>>(x, gw, (float*)d_out);
}

// round 15
// speedup vs baseline: 1.4032x; 1.4032x over previous
#include <cuda_runtime.h>
#include <math.h>

// Problem shape
#define HDIM     4096
#define EDIM     64
#define M_TOTAL  16384

// Tiling: grid 128 (1 CTA/SM), 256 threads (2 warps/SMSP — proven optimum),
// 8x4 thread tile (16-FFMA2 runs), KT=64 to halve per-tile phase overhead.
#define BM        128
#define KT        64
#define NT        (HDIM / KT)       // 64 K-tiles
#define NTHREADS  256

__global__ __launch_bounds__(NTHREADS, 1)
void router_kernel(const float* __restrict__ x,
                   const float* __restrict__ w,
                   float* __restrict__ out)
{
    // XOR-swizzled tiles (no padding): element (kk, r) at [kk][r ^ ((kk>>2 & 7)<<2)].
    // The swizzle constant wraps mod 32 in kk, so both k-halves of the KT=64 tile
    // use the identical conflict-free pattern proven in the KT=32 kernel.
    __shared__ union {
        struct {
            float xs[KT][BM];      // 32 KB
            float ws[KT][EDIM];    // 16 KB  (total 48 KB exactly)
        } t;
        float ls[BM][EDIM + 4];    // epilogue logits tile (stride 68)
    } sm;

    const int tid = threadIdx.x;
    const int m0  = blockIdx.x * BM;

    // compute mapping: thread tile = 8 rows x 4 experts
    const int eg = tid & 15;           // experts 4*eg .. 4*eg+3
    const int rg = tid >> 4;           // rows    8*rg .. 8*rg+7

    // x global-load mapping: 8 float4 per thread per tile (4 rows x 2 k-halves)
    const int xk4   = tid & 7;         // float4 index within k-half (0..7)
    const int xrow0 = tid >> 3;        // row 0..31, +32*i

    // w global-load mapping: 4 float4 per thread per tile (2 experts x 2 k-halves)
    const int wk4 = tid & 7;
    const int we0 = tid >> 3;          // expert 0..31, +32*i

    // swizzle constants on the store side: c = 4*k4 (same for all 4 components,
    // and identical for both k-halves since (k4+8)&7 == k4 after the >>2,&7 wrap)
    const int xsw = 4 * xk4;
    const int wsw = 4 * wk4;

    // accumulators: acc[row_pair][expert], packed f32x2 over (row, row+1)
    unsigned long long acc[4][4];
    #pragma unroll
    for (int i = 0; i < 4; i++)
        #pragma unroll
        for (int j = 0; j < 4; j++)
            acc[i][j] = 0ull;

    float4 xv[4][2], wv[2][2];         // [iter][k-half]

    // prefetch tile 0 into registers
    {
        const float* xp = x + (size_t)m0 * HDIM + 4 * xk4;
        #pragma unroll
        for (int i = 0; i < 4; i++) {
            const float* p = xp + (size_t)(xrow0 + 32 * i) * HDIM;
            xv[i][0] = *(const float4*)(p);
            xv[i][1] = *(const float4*)(p + 32);
        }
        const float* wp = w + 4 * wk4;
        #pragma unroll
        for (int i = 0; i < 2; i++) {
            const float* p = wp + (size_t)(we0 + 32 * i) * HDIM;
            wv[i][0] = *(const float4*)(p);
            wv[i][1] = *(const float4*)(p + 32);
        }
    }

    for (int t = 0; t < NT; t++) {
        // ---- store prefetched tile to smem (swizzled transpose, conflict-free) ----
        #pragma unroll
        for (int i = 0; i < 4; i++) {
            int rs = (xrow0 + 32 * i) ^ xsw;
            #pragma unroll
            for (int h = 0; h < 2; h++) {
                int kb = 4 * xk4 + 32 * h;
                sm.t.xs[kb + 0][rs] = xv[i][h].x;
                sm.t.xs[kb + 1][rs] = xv[i][h].y;
                sm.t.xs[kb + 2][rs] = xv[i][h].z;
                sm.t.xs[kb + 3][rs] = xv[i][h].w;
            }
        }
        #pragma unroll
        for (int i = 0; i < 2; i++) {
            int es = (we0 + 32 * i) ^ wsw;
            #pragma unroll
            for (int h = 0; h < 2; h++) {
                int kb = 4 * wk4 + 32 * h;
                sm.t.ws[kb + 0][es] = wv[i][h].x;
                sm.t.ws[kb + 1][es] = wv[i][h].y;
                sm.t.ws[kb + 2][es] = wv[i][h].z;
                sm.t.ws[kb + 3][es] = wv[i][h].w;
            }
        }
        __syncthreads();

        // ---- prefetch next global tile (overlaps the whole compute phase) ----
        if (t + 1 < NT) {
            const int k0 = (t + 1) * KT;
            const float* xp = x + (size_t)m0 * HDIM + k0 + 4 * xk4;
            #pragma unroll
            for (int i = 0; i < 4; i++) {
                const float* p = xp + (size_t)(xrow0 + 32 * i) * HDIM;
                xv[i][0] = *(const float4*)(p);
                xv[i][1] = *(const float4*)(p + 32);
            }
            const float* wp = w + k0 + 4 * wk4;
            #pragma unroll
            for (int i = 0; i < 2; i++) {
                const float* p = wp + (size_t)(we0 + 32 * i) * HDIM;
                wv[i][0] = *(const float4*)(p);
                wv[i][1] = *(const float4*)(p + 32);
            }
        }

        // ---- mainloop: 64 kk steps, 16 fma.rn.f32x2 each ----
        #pragma unroll
        for (int kk = 0; kk < KT; kk++) {
            const int c  = ((kk >> 2) & 7) << 2;    // compile-time per unrolled kk
            const int r1 = (8 * rg) ^ c;
            ulonglong2 xa = *(const ulonglong2*)&sm.t.xs[kk][r1];
            ulonglong2 xb = *(const ulonglong2*)&sm.t.xs[kk][r1 ^ 4];
            float4 wf = *(const float4*)&sm.t.ws[kk][(4 * eg) ^ c];

            unsigned long long xr[4];
            xr[0] = xa.x; xr[1] = xa.y; xr[2] = xb.x; xr[3] = xb.y;

            unsigned long long wd[4];
            asm("mov.b64 %0, {%1,%1};" : "=l"(wd[0]) : "r"(__float_as_uint(wf.x)));
            asm("mov.b64 %0, {%1,%1};" : "=l"(wd[1]) : "r"(__float_as_uint(wf.y)));
            asm("mov.b64 %0, {%1,%1};" : "=l"(wd[2]) : "r"(__float_as_uint(wf.z)));
            asm("mov.b64 %0, {%1,%1};" : "=l"(wd[3]) : "r"(__float_as_uint(wf.w)));

            #pragma unroll
            for (int rp = 0; rp < 4; rp++)
                #pragma unroll
                for (int e = 0; e < 4; e++)
                    asm("fma.rn.f32x2 %0, %1, %2, %0;"
                        : "+l"(acc[rp][e])
                        : "l"(xr[rp]), "l"(wd[e]));
        }
        __syncthreads();
    }

    // ---- epilogue ----
    float* logits_out = out;
    float* idx_out    = out + (size_t)M_TOTAL * EDIM;
    float* p_out      = idx_out + (size_t)M_TOTAL * 2;

    // rows here are UNswizzled — mainloop done, smem repurposed
    #pragma unroll
    for (int rp = 0; rp < 4; rp++) {
        #pragma unroll
        for (int e = 0; e < 4; e++) {
            unsigned int lo, hi;
            asm("mov.b64 {%0,%1}, %2;" : "=r"(lo), "=r"(hi) : "l"(acc[rp][e]));
            int r   = 8 * rg + 2 * rp;
            int col = 4 * eg + e;
            sm.ls[r][col]     = __uint_as_float(lo);
            sm.ls[r + 1][col] = __uint_as_float(hi);
        }
    }
    __syncthreads();

    // coalesced logits store: 8 x float4 per thread
    #pragma unroll
    for (int q = 0; q < 8; q++) {
        int idx = tid + NTHREADS * q;       // 0..2047 float4 slots
        int row = idx >> 4;
        int c4  = idx & 15;
        float4 v = *(const float4*)&sm.ls[row][c4 * 4];
        *(float4*)&logits_out[(size_t)(m0 + row) * EDIM + c4 * 4] = v;
    }

    // one thread per row: stable top-2 (strict >, ties -> lower index = lax.top_k)
    if (tid < BM) {
        const float* r = &sm.ls[tid][0];
        float best = -INFINITY, sec = -INFINITY;
        int bi = 0, si = 0;
        #pragma unroll 8
        for (int i = 0; i < EDIM; i++) {
            float v = r[i];
            if (v > best) { sec = best; si = bi; best = v; bi = i; }
            else if (v > sec) { sec = v; si = i; }
        }
        float tt  = expf(sec - best);
        float inv = 1.0f / (1.0f + tt);
        size_t m = (size_t)(m0 + tid);
        idx_out[m * 2 + 0] = (float)bi;
        idx_out[m * 2 + 1] = (float)si;
        p_out[m * 2 + 0]   = inv;
        p_out[m * 2 + 1]   = tt * inv;
    }
}

extern "C" void kernel_launch(void* const* d_in, const int* in_sizes, int n_in,
                              void* d_out, int out_size)
{
    const float* x  = (const float*)d_in[0];
    const float* gw = (const float*)d_in[1];
    // defensive: identify tensors by size (x = 67108864, gate_w = 262144)
    if (n_in >= 2 && in_sizes[0] < in_sizes[1]) {
        const float* tmp = x; x = gw; gw = tmp;
    }
    router_kernel<<<M_TOTAL / BM, NTHREADS>>>(x, gw, (float*)d_out);
}